// round 17
// baseline (speedup 1.0000x reference)
#include <cuda_runtime.h>

#define Hh 128
#define Ww 128
#define Cc 64
#define PAD 3
#define HP 134
#define WP 134
#define WS 7
#define SST 160
#define HPWP (HP * WP)
#define HW (Hh * Ww)

// ---------------- scratch (device globals; no allocation allowed) ----------
__device__ float g_qpad[Cc * HPWP];      // padded q  (C, HP, WP)
__device__ float g_kpad[Cc * HPWP];
__device__ float g_vpad[Cc * HPWP];
__device__ float g_T[HP * Hh * Ww];      // T[r][w][k] = sum_pj S_r[w+pj, k+pj]
__device__ float g_vsum[Cc * Hh * Ww];   // 7x7 box sum of vpad

#define HALO_PER_C 1572

// ---------------- kernel 1: halo-zero + q/k/v 1x1 conv --------------------
__global__ void __launch_bounds__(512) k_qkv(
        const float* __restrict__ x,
        const float* __restrict__ Wq, const float* __restrict__ bq,
        const float* __restrict__ Wk, const float* __restrict__ bk,
        const float* __restrict__ Wv, const float* __restrict__ bv) {
    // ---- fused halo zeroing (disjoint from interior writes; no race) ----
    {
        const int t = blockIdx.x * 512 + threadIdx.x;   // 131072 >= 100608
        if (t < Cc * HALO_PER_C) {
            const int c = t / HALO_PER_C;
            const int e = t - c * HALO_PER_C;
            int row, w;
            if (e < 804) {
                const int r6 = e / 134;
                w = e - r6 * 134;
                row = (r6 < 3) ? r6 : r6 + 128;
            } else {
                const int f = e - 804;
                const int q = f >> 7;
                w = (q < 3) ? q : q + 128;
                row = (f & 127) + 3;
            }
            const int idx = c * HPWP + row * WP + w;
            g_qpad[idx] = 0.f; g_kpad[idx] = 0.f; g_vpad[idx] = 0.f;
        }
    }

    __shared__ float sW[3 * Cc * Cc];   // 48 KB
    float* sWq = sW;
    float* sWk = sW + Cc * Cc;
    float* sWv = sW + 2 * Cc * Cc;
    for (int i = threadIdx.x; i < Cc * Cc; i += 512) {
        sWq[i] = Wq[i]; sWk[i] = Wk[i]; sWv[i] = Wv[i];
    }
    __syncthreads();

    const int tid  = threadIdx.x;
    const int p    = tid & 31;
    const int warp = tid >> 5;
    const int og   = (warp & 7) * 8;
    const int pg   = (warp >> 3) * 32;
    const int s    = blockIdx.x * 64 + pg + p;
    const int h = s >> 7, w = s & 127;
    const int po = (h + PAD) * WP + (w + PAD);

    float xv[Cc];
#pragma unroll
    for (int c = 0; c < Cc; c++) xv[c] = x[c * HW + s];

#pragma unroll
    for (int oo = 0; oo < 8; oo++) {
        const int o = og + oo;
        float aq = __ldg(&bq[o]), ak = __ldg(&bk[o]), av = __ldg(&bv[o]);
#pragma unroll
        for (int c = 0; c < Cc; c++) {
            const float xc = xv[c];
            aq += sWq[o * Cc + c] * xc;
            ak += sWk[o * Cc + c] * xc;
            av += sWv[o * Cc + c] * xc;
        }
        g_qpad[o * HPWP + po] = aq;
        g_kpad[o * HPWP + po] = ak;
        g_vpad[o * HPWP + po] = av;
    }
}

// ---------------- kernel 2: fused separable 7x7 box of vpad -> vsum --------
__global__ void k_box() {
    __shared__ float sv[22 * 136];
    __shared__ float hs[22 * 128];
    const int c = blockIdx.x >> 3;
    const int h0 = (blockIdx.x & 7) * 16;
    const int tid = threadIdx.x;

    for (int i = tid; i < 22 * WP; i += 256) {
        const int rr = i / WP, w = i - rr * WP;
        sv[rr * 136 + w] = g_vpad[c * HPWP + (h0 + rr) * WP + w];
    }
    __syncthreads();
    for (int i = tid; i < 22 * 128; i += 256) {
        const int rr = i >> 7, k = i & 127;
        float s = 0.f;
#pragma unroll
        for (int p = 0; p < WS; p++) s += sv[rr * 136 + k + p];
        hs[i] = s;
    }
    __syncthreads();
    for (int i = tid; i < 16 * 128; i += 256) {
        const int hh = i >> 7, k = i & 127;
        float s = 0.f;
#pragma unroll
        for (int p = 0; p < WS; p++) s += hs[(hh + p) * 128 + k];
        g_vsum[(c * Hh + h0 + hh) * Ww + k] = s;
    }
}

// ---------------- kernel 3: per-row Gram matrix + diagonal 7-band sum ------
// grid = HP, block 384. 16(w) x 24(k) tiles of 9x6.
__global__ void __launch_bounds__(384, 1) k_gram() {
    extern __shared__ float sm[];
    float* sQ = sm;                      // [64][160]
    float* sK = sm + Cc * SST;           // [64][160]
    float* sS = sm + 2 * Cc * SST;       // [144][160]
    const int r = blockIdx.x;
    const int tid = threadIdx.x;

    for (int i = tid; i < Cc * SST; i += 384) {
        const int c = i / SST, w = i - c * SST;
        float qv = 0.f, kv = 0.f;
        if (w < WP) {
            qv = g_qpad[c * HPWP + r * WP + w];
            kv = g_kpad[c * HPWP + r * WP + w];
        }
        sQ[i] = qv; sK[i] = kv;
    }
    __syncthreads();

    {
        const int kt = tid % 24, wt = tid / 24;
        const int k0 = kt * 6, w0 = wt * 9;
        float acc[9][6];
#pragma unroll
        for (int i = 0; i < 9; i++)
#pragma unroll
            for (int j = 0; j < 6; j++) acc[i][j] = 0.f;

#pragma unroll 2
        for (int c = 0; c < Cc; c++) {
            float q[9], kk[6];
#pragma unroll
            for (int i = 0; i < 9; i++) q[i] = sQ[c * SST + w0 + i];
#pragma unroll
            for (int j = 0; j < 6; j++) kk[j] = sK[c * SST + k0 + j];
#pragma unroll
            for (int i = 0; i < 9; i++)
#pragma unroll
                for (int j = 0; j < 6; j++) acc[i][j] += q[i] * kk[j];
        }
#pragma unroll
        for (int i = 0; i < 9; i++)
#pragma unroll
            for (int j = 0; j < 6; j++)
                sS[(w0 + i) * SST + k0 + j] = acc[i][j];
    }
    __syncthreads();

    for (int o = tid; o < HW; o += 384) {
        const int w = o >> 7, k = o & 127;
        float s = 0.f;
#pragma unroll
        for (int p = 0; p < WS; p++) s += sS[(w + p) * SST + (k + p)];
        g_T[r * HW + o] = s;
    }
}

// ---------------- kernel 4: FUSED logits + softmax + attn@vsum GEMM --------
// grid = 256 (h x 2 w-halves), block 256 (8 warps), dyn smem 68608 B
// -> 3 CTAs/SM resident; all 256 CTAs co-resident (latency overlap).
// Phase 3: warp owns 8 channels (2x LDS.128 broadcast from sV, stride 68);
// lane owns w in {l, l+32}; k skewed (banks 5l+t: conflict-free).
__global__ void __launch_bounds__(256) k_out(float* __restrict__ out) {
    extern __shared__ float sm[];
    float* sL = sm;                 // [64(w-local)][132]  logits -> attn
    float* sV = sm + 64 * 132;      // [128(k)][68]  vsum transposed (16B-aligned rows)
    const int h  = blockIdx.x >> 1;
    const int wb = (blockIdx.x & 1) * 64;
    const int tid = threadIdx.x;
    const int lane = tid & 31;
    const int ww = tid >> 5;        // 0..7

    // stage sV[k][c] (stride 68: rows 16B-aligned for LDS.128)
    for (int i = tid; i < Cc * Ww; i += 256) {
        const int c = i >> 7, k = i & 127;
        sV[k * 68 + c] = g_vsum[(c * Hh + h) * Ww + k];
    }
    // phase 1: vertical 7-sum of T for this CTA's 64 w's (float4)
    for (int i = tid; i < 2048; i += 256) {
        const int wl = i >> 5, k4 = (i & 31) * 4;
        const int g = (wb + wl) * Ww + k4;
        float4 a = *(const float4*)&g_T[h * HW + g];
#pragma unroll
        for (int p = 1; p < WS; p++) {
            const float4 t = *(const float4*)&g_T[(h + p) * HW + g];
            a.x += t.x; a.y += t.y; a.z += t.z; a.w += t.w;
        }
        *(float4*)&sL[wl * 132 + k4] = a;
    }
    __syncthreads();

    // phase 2: softmax over k, 8 rows per warp
#pragma unroll
    for (int rr = 0; rr < 8; rr++) {
        const int w = ww * 8 + rr;
        float4 v = *(float4*)&sL[w * 132 + 4 * lane];
        float m = fmaxf(fmaxf(v.x, v.y), fmaxf(v.z, v.w));
#pragma unroll
        for (int off = 16; off; off >>= 1)
            m = fmaxf(m, __shfl_xor_sync(0xffffffffu, m, off));
        float4 e;
        e.x = __expf(v.x - m); e.y = __expf(v.y - m);
        e.z = __expf(v.z - m); e.w = __expf(v.w - m);
        float s = e.x + e.y + e.z + e.w;
#pragma unroll
        for (int off = 16; off; off >>= 1)
            s += __shfl_xor_sync(0xffffffffu, s, off);
        const float inv = 1.0f / s;
        e.x *= inv; e.y *= inv; e.z *= inv; e.w *= inv;
        *(float4*)&sL[w * 132 + 4 * lane] = e;
    }
    __syncthreads();

    // phase 3: out[c, h, wb+w] = sum_k attn[w][k] * vsum[c][k]
    const int c0 = ww * 8;          // warp's 8 channels
    float acc[8][2];
#pragma unroll
    for (int i = 0; i < 8; i++) { acc[i][0] = 0.f; acc[i][1] = 0.f; }

#pragma unroll 2
    for (int t = 0; t < 128; t++) {
        const int kk = (t + lane) & 127;
        const float4 v0 = *(const float4*)&sV[kk * 68 + c0];      // broadcast
        const float4 v1 = *(const float4*)&sV[kk * 68 + c0 + 4];  // broadcast
        const float a0 = sL[lane * 132 + kk];                     // cf (5l+t)
        const float a1 = sL[(lane + 32) * 132 + kk];              // cf
        const float vr[8] = {v0.x, v0.y, v0.z, v0.w, v1.x, v1.y, v1.z, v1.w};
#pragma unroll
        for (int i = 0; i < 8; i++) {
            acc[i][0] += vr[i] * a0;
            acc[i][1] += vr[i] * a1;
        }
    }
#pragma unroll
    for (int i = 0; i < 8; i++) {
        out[(c0 + i) * HW + h * Ww + wb + lane]      = acc[i][0];
        out[(c0 + i) * HW + h * Ww + wb + lane + 32] = acc[i][1];
    }
}

// ---------------------------------------------------------------------------
extern "C" void kernel_launch(void* const* d_in, const int* in_sizes, int n_in,
                              void* d_out, int out_size) {
    const float* x  = (const float*)d_in[0];
    const float* Wq = (const float*)d_in[1];
    const float* bq = (const float*)d_in[2];
    const float* Wk = (const float*)d_in[3];
    const float* bk = (const float*)d_in[4];
    const float* Wv = (const float*)d_in[5];
    const float* bv = (const float*)d_in[6];
    float* out = (float*)d_out;

    const int smemB = (2 * Cc * SST + 144 * SST) * 4;   // 174080
    const int smemE = (64 * 132 + 128 * 68) * 4;        // 68608
    cudaFuncSetAttribute(k_gram, cudaFuncAttributeMaxDynamicSharedMemorySize, smemB);
    cudaFuncSetAttribute(k_out,  cudaFuncAttributeMaxDynamicSharedMemorySize, smemE);

    k_qkv<<<(Hh * Ww) / 64, 512>>>(x, Wq, bq, Wk, bk, Wv, bv); // #1 (+halo zero)
    k_box<<<Cc * 8, 256>>>();                             // #2
    k_gram<<<HP, 384, smemB>>>();                         // #3
    k_out<<<Hh * 2, 256, smemE>>>(out);                   // #4 <- ncu slot
}